// round 2
// baseline (speedup 1.0000x reference)
#include <cuda_runtime.h>
#include <cstdint>

// ---------------------------------------------------------------------------
// HeteroGraph: 2-layer GraphConv (loop + fwd-edge + rev-edge relations) + mean
// readout per graph.
//
//   per layer:  y = h@W0 + spmm_fwd(h)@W1 + spmm_bwd(h)@W2 + (b0+b1+b2)
//               h = relu(y)
//   spmm_fwd:   agg1[dst] += n_out[src]*n_in[dst] * h[src]
//   spmm_bwd:   agg2[src] += n_out[src]*n_in[dst] * h[dst]   (same coefficient)
//   readout:    out[g] = mean over nodes with graph_ids==g (sorted ids)
// ---------------------------------------------------------------------------

#define DIM 128
#define NMAX 500128            // 500000 + pad
#define GKK 32                 // k-chunk
#define XS_STRIDE 132          // padded row stride in Xs (mod 32 != 0, 16B aligned)
#define SMEM_BYTES ((384*128 + GKK*XS_STRIDE) * 4)

// Static scratch (allocations are forbidden; __device__ globals are the workaround)
__device__ float g_h[(size_t)NMAX * DIM];      // hidden state (in-place across layers)
__device__ float g_agg1[(size_t)NMAX * DIM];
__device__ float g_agg2[(size_t)NMAX * DIM];
__device__ float g_outdeg[NMAX];
__device__ float g_indeg[NMAX];

// ---------------------------------------------------------------------------
__global__ void degree_kernel(const int* __restrict__ src, const int* __restrict__ dst,
                              float* odeg, float* ideg, int E) {
    int e = blockIdx.x * blockDim.x + threadIdx.x;
    if (e < E) {
        atomicAdd(&odeg[src[e]], 1.0f);
        atomicAdd(&ideg[dst[e]], 1.0f);
    }
}

__global__ void norm_kernel(float* odeg, float* ideg, int N) {
    int i = blockIdx.x * blockDim.x + threadIdx.x;
    if (i < N) {
        float a = odeg[i];
        odeg[i] = (a > 0.0f) ? rsqrtf(a) : 0.0f;
        float b = ideg[i];
        ideg[i] = (b > 0.0f) ? rsqrtf(b) : 0.0f;
    }
}

// One warp per edge; both directions in one pass (shared coefficient).
__global__ void spmm_kernel(const float* __restrict__ h,
                            const int* __restrict__ src, const int* __restrict__ dst,
                            const float* __restrict__ n_out, const float* __restrict__ n_in,
                            float* __restrict__ agg1, float* __restrict__ agg2, int E) {
    int e = (blockIdx.x * blockDim.x + threadIdx.x) >> 5;
    if (e >= E) return;
    int lane = threadIdx.x & 31;
    int s = src[e];
    int d = dst[e];
    float c = n_out[s] * n_in[d];

    const float4 hs = *(const float4*)(h + (size_t)s * DIM + lane * 4);
    const float4 hd = *(const float4*)(h + (size_t)d * DIM + lane * 4);

    float* a1 = agg1 + (size_t)d * DIM + lane * 4;
    float* a2 = agg2 + (size_t)s * DIM + lane * 4;
    atomicAdd(a1 + 0, c * hs.x);
    atomicAdd(a1 + 1, c * hs.y);
    atomicAdd(a1 + 2, c * hs.z);
    atomicAdd(a1 + 3, c * hs.w);
    atomicAdd(a2 + 0, c * hd.x);
    atomicAdd(a2 + 1, c * hd.y);
    atomicAdd(a2 + 2, c * hd.z);
    atomicAdd(a2 + 3, c * hd.w);
}

// ---------------------------------------------------------------------------
// Fused GEMM:  Y[N,128] = relu( X0@W0 + X1@W1 + X2@W2 + (b0+b1+b2) )
// Treated as [N,384] @ [384,128]. Full W (384x128 f32 = 192KB) staged in smem.
// Block: 256 threads, 128 rows. Thread tile: 8 rows x 8 cols, packed f32x2 FMA.
// NOTE: Y may alias X0 — each block reads X0 only within its own 128-row tile
// and writes those rows only in the epilogue (after all reads).
// ---------------------------------------------------------------------------
__global__ __launch_bounds__(256) void gemm_kernel(
    const float* __restrict__ X0, const float* __restrict__ X1, const float* __restrict__ X2,
    const float* __restrict__ Wl,   // [3,128,128] flat = [384,128]
    const float* __restrict__ bl,   // [3,128]
    float* __restrict__ Y, int N)
{
    extern __shared__ float sm[];
    float* Ws = sm;                    // 384*128
    float* Xs = sm + 384 * 128;        // GKK * XS_STRIDE (k-major, padded)

    const int tid  = threadIdx.x;
    const int row0 = blockIdx.x * 128;
    const int tc   = tid & 15;         // col group: cols tc*8 .. +7
    const int tr   = tid >> 4;         // row group: rows tr*8 .. +7
    const int lrow = tid & 31;         // transpose-load row lane
    const int k4   = (tid >> 5) * 4;   // transpose-load k base (0..28)

    // Stage W into smem (straight copy: [r][k][j] flattens to [384,128])
    for (int idx = tid * 4; idx < 384 * 128; idx += 256 * 4)
        *(float4*)(Ws + idx) = *(const float4*)(Wl + idx);

    unsigned long long acc[8][4];
#pragma unroll
    for (int i = 0; i < 8; i++)
#pragma unroll
        for (int jp = 0; jp < 4; jp++) acc[i][jp] = 0ull;

    float4 pre[4];
    // Prefetch chunk 0 (from X0)
    {
#pragma unroll
        for (int it = 0; it < 4; it++) {
            int r = lrow + it * 32;
            int grow = row0 + r; if (grow > N - 1) grow = N - 1;
            pre[it] = *(const float4*)(X0 + (size_t)grow * DIM + k4);
        }
    }

#pragma unroll 1
    for (int c = 0; c < 12; c++) {
        // Transposed store into Xs: addr = k*XS_STRIDE + row (conflict-free: rows 0..31/warp)
#pragma unroll
        for (int it = 0; it < 4; it++) {
            int r = lrow + it * 32;
            Xs[(k4 + 0) * XS_STRIDE + r] = pre[it].x;
            Xs[(k4 + 1) * XS_STRIDE + r] = pre[it].y;
            Xs[(k4 + 2) * XS_STRIDE + r] = pre[it].z;
            Xs[(k4 + 3) * XS_STRIDE + r] = pre[it].w;
        }
        __syncthreads();

        // Prefetch next chunk while computing this one
        if (c < 11) {
            int cn = c + 1;
            const float* Xp = (cn < 4) ? X0 : ((cn < 8) ? X1 : X2);
            int kk0 = (cn & 3) * GKK + k4;
#pragma unroll
            for (int it = 0; it < 4; it++) {
                int r = lrow + it * 32;
                int grow = row0 + r; if (grow > N - 1) grow = N - 1;
                pre[it] = *(const float4*)(Xp + (size_t)grow * DIM + kk0);
            }
        }

        const float* wbase = Ws + (c * GKK) * 128 + tc * 8;
        const float* xbase = Xs + tr * 8;
#pragma unroll 8
        for (int k = 0; k < GKK; k++) {
            float4 xa = *(const float4*)(xbase + k * XS_STRIDE);
            float4 xb = *(const float4*)(xbase + k * XS_STRIDE + 4);
            ulonglong2 w01 = *(const ulonglong2*)(wbase + k * 128);
            ulonglong2 w23 = *(const ulonglong2*)(wbase + k * 128 + 4);
            unsigned long long wp0 = w01.x, wp1 = w01.y, wp2 = w23.x, wp3 = w23.y;
            float xv[8] = {xa.x, xa.y, xa.z, xa.w, xb.x, xb.y, xb.z, xb.w};
#pragma unroll
            for (int i = 0; i < 8; i++) {
                unsigned long long xd;
                asm("mov.b64 %0, {%1, %1};" : "=l"(xd) : "f"(xv[i]));
                asm("fma.rn.f32x2 %0, %1, %2, %0;" : "+l"(acc[i][0]) : "l"(xd), "l"(wp0));
                asm("fma.rn.f32x2 %0, %1, %2, %0;" : "+l"(acc[i][1]) : "l"(xd), "l"(wp1));
                asm("fma.rn.f32x2 %0, %1, %2, %0;" : "+l"(acc[i][2]) : "l"(xd), "l"(wp2));
                asm("fma.rn.f32x2 %0, %1, %2, %0;" : "+l"(acc[i][3]) : "l"(xd), "l"(wp3));
            }
        }
        __syncthreads();
    }

    // Epilogue: bias sum + relu + store
    float bs[8];
#pragma unroll
    for (int jj = 0; jj < 8; jj++) {
        int col = tc * 8 + jj;
        bs[jj] = bl[col] + bl[128 + col] + bl[256 + col];
    }
#pragma unroll
    for (int i = 0; i < 8; i++) {
        int grow = row0 + tr * 8 + i;
        if (grow < N) {
            float o[8];
#pragma unroll
            for (int jp = 0; jp < 4; jp++) {
                union { unsigned long long u; float2 f; } cv;
                cv.u = acc[i][jp];
                o[jp * 2]     = cv.f.x;
                o[jp * 2 + 1] = cv.f.y;
            }
#pragma unroll
            for (int jj = 0; jj < 8; jj++) o[jj] = fmaxf(o[jj] + bs[jj], 0.0f);
            float* yp = Y + (size_t)grow * DIM + tc * 8;
            *(float4*)(yp)     = make_float4(o[0], o[1], o[2], o[3]);
            *(float4*)(yp + 4) = make_float4(o[4], o[5], o[6], o[7]);
        }
    }
}

// ---------------------------------------------------------------------------
// Readout: graph_ids are sorted -> block per graph, binary search range, mean.
// ---------------------------------------------------------------------------
__device__ __forceinline__ int lower_bound_i(const int* a, int n, int v) {
    int lo = 0, hi = n;
    while (lo < hi) {
        int m = (lo + hi) >> 1;
        if (a[m] < v) lo = m + 1; else hi = m;
    }
    return lo;
}

__global__ void readout_kernel(const float* __restrict__ h, const int* __restrict__ gid,
                               float* __restrict__ out, int N) {
    int g = blockIdx.x;
    __shared__ int bounds[2];
    if (threadIdx.x == 0) {
        bounds[0] = lower_bound_i(gid, N, g);
        bounds[1] = lower_bound_i(gid, N, g + 1);
    }
    __syncthreads();
    int lo = bounds[0], hi = bounds[1];
    float s = 0.0f;
    for (int r = lo; r < hi; r++)
        s += h[(size_t)r * DIM + threadIdx.x];
    float cnt = (float)(hi - lo);
    out[(size_t)g * DIM + threadIdx.x] = s / fmaxf(cnt, 1.0f);
}

// ---------------------------------------------------------------------------
extern "C" void kernel_launch(void* const* d_in, const int* in_sizes, int n_in,
                              void* d_out, int out_size) {
    const float* feat = (const float*)d_in[0];   // [N,128]
    const float* W    = (const float*)d_in[1];   // [2,3,128,128]
    const float* b    = (const float*)d_in[2];   // [2,3,128]
    const int*   esrc = (const int*)d_in[3];     // [E]
    const int*   edst = (const int*)d_in[4];     // [E]
    const int*   gids = (const int*)d_in[5];     // [N] sorted

    const int N = in_sizes[0] / DIM;
    const int E = in_sizes[3];
    const int G = out_size / DIM;

    float *h, *a1, *a2, *odeg, *ideg;
    cudaGetSymbolAddress((void**)&h,    g_h);
    cudaGetSymbolAddress((void**)&a1,   g_agg1);
    cudaGetSymbolAddress((void**)&a2,   g_agg2);
    cudaGetSymbolAddress((void**)&odeg, g_outdeg);
    cudaGetSymbolAddress((void**)&ideg, g_indeg);

    cudaFuncSetAttribute(gemm_kernel, cudaFuncAttributeMaxDynamicSharedMemorySize, SMEM_BYTES);

    // Degrees -> norms
    cudaMemsetAsync(odeg, 0, (size_t)N * sizeof(float));
    cudaMemsetAsync(ideg, 0, (size_t)N * sizeof(float));
    degree_kernel<<<(E + 255) / 256, 256>>>(esrc, edst, odeg, ideg, E);
    norm_kernel<<<(N + 255) / 256, 256>>>(odeg, ideg, N);

    const float* hin = feat;
    for (int l = 0; l < 2; l++) {
        cudaMemsetAsync(a1, 0, (size_t)N * DIM * sizeof(float));
        cudaMemsetAsync(a2, 0, (size_t)N * DIM * sizeof(float));
        long long threads = (long long)E * 32;
        int blocks = (int)((threads + 255) / 256);
        spmm_kernel<<<blocks, 256>>>(hin, esrc, edst, odeg, ideg, a1, a2, E);
        // In-place: layer 0 reads feat, writes h; layer 1 reads h, writes h.
        gemm_kernel<<<(N + 127) / 128, 256, SMEM_BYTES>>>(
            hin, a1, a2, W + (size_t)l * 3 * 128 * 128, b + (size_t)l * 3 * 128,
            h, N);
        hin = h;
    }

    readout_kernel<<<G, DIM>>>(h, gids, (float*)d_out, N);
}

// round 4
// speedup vs baseline: 2.0122x; 2.0122x over previous
#include <cuda_runtime.h>
#include <cuda_bf16.h>
#include <cstdint>

// ---------------------------------------------------------------------------
// HeteroGraph: 2-layer GraphConv (loop + fwd + rev relations) + mean readout.
// Restructured per layer (spmm commutes with dense matmul):
//   GEMM:  T0 = act(h)@W0 + (b0+b1+b2) -> Y ;  Z1 = act(h)@W1 ; Z2 = act(h)@W2
//   SPMM:  Y[dst] += c*Z1[src] ;  Y[src] += c*Z2[dst]   (c = n_out[s]*n_in[d])
// act = relu for layer>0, identity for layer 0. Readout applies relu.
// GEMM on legacy tensor cores: mma.sync bf16 with 3-term hi/lo split.
// ---------------------------------------------------------------------------

#define DIM 128
#define NMAX 500128
#define TILE_M 128

// smem layout (bytes): A_hi 32K | A_lo 32K | B_hi 16K | B_lo 16K | bias 512
#define SM_AHI 0
#define SM_ALO 32768
#define SM_B   65536
#define SM_BIAS 98304
#define GEMM_SMEM (98304 + 512)

// Static scratch
__device__ float g_y[(size_t)NMAX * DIM];
__device__ float g_z1[(size_t)NMAX * DIM];
__device__ float g_z2[(size_t)NMAX * DIM];
__device__ float g_outdeg[NMAX];
__device__ float g_indeg[NMAX];
// Prepacked W^T images: [layer][group(6)][prec(2)][16KB] ; group = 64 output cols
__device__ uint4 g_wpack[2][6][2][1024];

// ---------------------------------------------------------------------------
__device__ __forceinline__ uint32_t smem_u32(const void* p) {
    uint32_t a;
    asm("{ .reg .u64 t; cvta.to.shared.u64 t, %1; cvt.u32.u64 %0, t; }" : "=r"(a) : "l"(p));
    return a;
}
__device__ __forceinline__ void ldsm4(uint32_t* r, uint32_t addr) {
    asm volatile("ldmatrix.sync.aligned.m8n8.x4.shared.b16 {%0,%1,%2,%3}, [%4];"
                 : "=r"(r[0]), "=r"(r[1]), "=r"(r[2]), "=r"(r[3]) : "r"(addr));
}
__device__ __forceinline__ void mma_bf16(float* d, const uint32_t* a, uint32_t b0, uint32_t b1) {
    asm volatile("mma.sync.aligned.m16n8k16.row.col.f32.bf16.bf16.f32 "
                 "{%0,%1,%2,%3}, {%4,%5,%6,%7}, {%8,%9}, {%0,%1,%2,%3};"
                 : "+f"(d[0]), "+f"(d[1]), "+f"(d[2]), "+f"(d[3])
                 : "r"(a[0]), "r"(a[1]), "r"(a[2]), "r"(a[3]), "r"(b0), "r"(b1));
}
__device__ __forceinline__ unsigned short bf16_bits(float v) {
    __nv_bfloat16 h = __float2bfloat16(v);
    return *(unsigned short*)&h;
}
__device__ __forceinline__ float bf16_val(unsigned short b) {
    __nv_bfloat16 h = *(__nv_bfloat16*)&b;
    return __bfloat162float(h);
}

// ---------------------------------------------------------------------------
// Prepack W: image rows = output col n (within 64-col group), 256B of K=128 bf16,
// 16B chunks XOR-swizzled by (n&7). hi/lo split.
// ---------------------------------------------------------------------------
__global__ void prepack_kernel(const float* __restrict__ W) {
    int idx = blockIdx.x * blockDim.x + threadIdx.x;   // 2*384*128
    if (idx >= 2 * 384 * 128) return;
    int k = idx & 127;
    int J = (idx >> 7) % 384;
    int l = idx / (384 * 128);
    int r = J >> 7, j = J & 127;
    int g = J >> 6, n = J & 63;
    float v = W[(((size_t)l * 3 + r) * 128 + k) * 128 + j];
    unsigned short hb = bf16_bits(v);
    unsigned short lb = bf16_bits(v - bf16_val(hb));
    uint32_t off = n * 256 + (((k >> 3) ^ (n & 7)) << 4) + (k & 7) * 2;
    *(unsigned short*)((unsigned char*)&g_wpack[l][g][0][0] + off) = hb;
    *(unsigned short*)((unsigned char*)&g_wpack[l][g][1][0] + off) = lb;
}

// ---------------------------------------------------------------------------
__global__ void degree_kernel(const int* __restrict__ src, const int* __restrict__ dst,
                              float* odeg, float* ideg, int E) {
    int e = blockIdx.x * blockDim.x + threadIdx.x;
    if (e < E) {
        atomicAdd(&odeg[src[e]], 1.0f);
        atomicAdd(&ideg[dst[e]], 1.0f);
    }
}
__global__ void norm_kernel(float* odeg, float* ideg, int N) {
    int i = blockIdx.x * blockDim.x + threadIdx.x;
    if (i < N) {
        float a = odeg[i]; odeg[i] = (a > 0.0f) ? rsqrtf(a) : 0.0f;
        float b = ideg[i]; ideg[i] = (b > 0.0f) ? rsqrtf(b) : 0.0f;
    }
}

// One warp per edge; both directions; accumulate straight into Y.
__global__ void spmm_kernel(const float* __restrict__ z1, const float* __restrict__ z2,
                            const int* __restrict__ src, const int* __restrict__ dst,
                            const float* __restrict__ n_out, const float* __restrict__ n_in,
                            float* __restrict__ y, int E) {
    int e = (blockIdx.x * blockDim.x + threadIdx.x) >> 5;
    if (e >= E) return;
    int lane = threadIdx.x & 31;
    int s = src[e];
    int d = dst[e];
    float c = n_out[s] * n_in[d];
    const float4 zs = *(const float4*)(z1 + (size_t)s * DIM + lane * 4);
    const float4 zd = *(const float4*)(z2 + (size_t)d * DIM + lane * 4);
    float* yd = y + (size_t)d * DIM + lane * 4;
    float* ys = y + (size_t)s * DIM + lane * 4;
    atomicAdd(yd + 0, c * zs.x); atomicAdd(yd + 1, c * zs.y);
    atomicAdd(yd + 2, c * zs.z); atomicAdd(yd + 3, c * zs.w);
    atomicAdd(ys + 0, c * zd.x); atomicAdd(ys + 1, c * zd.y);
    atomicAdd(ys + 2, c * zd.z); atomicAdd(ys + 3, c * zd.w);
}

// ---------------------------------------------------------------------------
// Tensor GEMM: per 128-row tile computes [128,384] = act(X)@[128,384] where
// cols 0-127 -> Y (+bias), 128-255 -> Z1, 256-383 -> Z2.
// 8 warps: warp tile 32x32 within a 64-col group; 6 groups sequential.
// 3-term bf16 split: Ahi*Bhi + Ahi*Blo + Alo*Bhi, fp32 accumulate.
// Y may alias X: each CTA reads only its own 128 rows (at kernel start) and
// writes them only in epilogues.
// ---------------------------------------------------------------------------
__global__ __launch_bounds__(256, 2) void gemm3_kernel(
    const float* X, const uint4* __restrict__ wpack,   // [6][2][1024]
    const float* __restrict__ bl,                      // [3,128]
    float* Y, float* __restrict__ Z1, float* __restrict__ Z2,
    int N, int relu_in)
{
    extern __shared__ char smem[];
    const uint32_t sb = smem_u32(smem);
    const int tid = threadIdx.x;
    const int wid = tid >> 5;
    const int lane = tid & 31;
    const int row0 = blockIdx.x * TILE_M;

    // ---- bias sums ----
    if (tid < 128) {
        *(float*)(smem + SM_BIAS + tid * 4) = bl[tid] + bl[128 + tid] + bl[256 + tid];
    }

    // ---- A fill: 128 rows x 128 k fp32 -> hi/lo bf16, swizzled ----
    {
        const int r = tid >> 1;
        const int khalf = (tid & 1) * 64;
        int grow = row0 + r; if (grow > N - 1) grow = N - 1;
        const float* srcp = X + (size_t)grow * DIM + khalf;
#pragma unroll
        for (int c8 = 0; c8 < 8; c8++) {
            float4 va = *(const float4*)(srcp + c8 * 8);
            float4 vb = *(const float4*)(srcp + c8 * 8 + 4);
            float v[8] = {va.x, va.y, va.z, va.w, vb.x, vb.y, vb.z, vb.w};
            if (relu_in) {
#pragma unroll
                for (int i = 0; i < 8; i++) v[i] = fmaxf(v[i], 0.0f);
            }
            unsigned short hb[8], lb[8];
#pragma unroll
            for (int i = 0; i < 8; i++) {
                hb[i] = bf16_bits(v[i]);
                lb[i] = bf16_bits(v[i] - bf16_val(hb[i]));
            }
            uint4 hq, lq;
            hq.x = (uint32_t)hb[0] | ((uint32_t)hb[1] << 16);
            hq.y = (uint32_t)hb[2] | ((uint32_t)hb[3] << 16);
            hq.z = (uint32_t)hb[4] | ((uint32_t)hb[5] << 16);
            hq.w = (uint32_t)hb[6] | ((uint32_t)hb[7] << 16);
            lq.x = (uint32_t)lb[0] | ((uint32_t)lb[1] << 16);
            lq.y = (uint32_t)lb[2] | ((uint32_t)lb[3] << 16);
            lq.z = (uint32_t)lb[4] | ((uint32_t)lb[5] << 16);
            lq.w = (uint32_t)lb[6] | ((uint32_t)lb[7] << 16);
            int cc = (khalf >> 3) + c8;                  // 16B chunk index 0..15
            int off = r * 256 + ((cc ^ (r & 7)) << 4);
            *(uint4*)(smem + SM_AHI + off) = hq;
            *(uint4*)(smem + SM_ALO + off) = lq;
        }
    }
    __syncthreads();

    const int mgrp = wid & 3;       // row group (32 rows)
    const int ngrp = wid >> 2;      // col group within 64 (32 cols)

    // Per-lane ldmatrix address components
    // A: lanes 0-15 -> rows (lane&15), k-chunk +0 ; lanes 16-31 -> same rows, +1
    const int arow[2] = { mgrp * 32 + 0 * 16 + (lane & 15), mgrp * 32 + 1 * 16 + (lane & 15) };
    const int ahi16 = lane >> 4;
    // B: within x4 for half h: lanes 0-7: n(+0-7) kc+0 ; 8-15: same n, kc+1 ;
    //    16-23: n(+8-15) kc+0 ; 24-31: kc+1
    const int brow_base = ngrp * 32 + (lane & 7) + ((lane >> 4) & 1) * 8;
    const int bk = (lane >> 3) & 1;

    const float* bias = (const float*)(smem + SM_BIAS);

#pragma unroll 1
    for (int g = 0; g < 6; g++) {
        // ---- load B group (hi 16KB + lo 16KB, already smem-image layout) ----
        {
            const uint4* wsrc = wpack + (size_t)g * 2048;
            uint4* bdst = (uint4*)(smem + SM_B);
#pragma unroll
            for (int i = tid; i < 2048; i += 256) bdst[i] = wsrc[i];
        }
        __syncthreads();

        float acc[2][4][4];
#pragma unroll
        for (int mt = 0; mt < 2; mt++)
#pragma unroll
            for (int nt = 0; nt < 4; nt++)
#pragma unroll
                for (int q = 0; q < 4; q++) acc[mt][nt][q] = 0.0f;

#pragma unroll
        for (int ks = 0; ks < 8; ks++) {
            uint32_t ah[2][4], al[2][4], bh[2][4], blo[2][4];
#pragma unroll
            for (int mt = 0; mt < 2; mt++) {
                uint32_t co = ((uint32_t)((ks * 2 + ahi16) ^ (arow[mt] & 7))) << 4;
                ldsm4(ah[mt], sb + SM_AHI + arow[mt] * 256 + co);
                ldsm4(al[mt], sb + SM_ALO + arow[mt] * 256 + co);
            }
#pragma unroll
            for (int h = 0; h < 2; h++) {
                int br = brow_base + h * 16;
                uint32_t co = ((uint32_t)((ks * 2 + bk) ^ (br & 7))) << 4;
                ldsm4(bh[h],  sb + SM_B +         br * 256 + co);
                ldsm4(blo[h], sb + SM_B + 16384 + br * 256 + co);
            }
#pragma unroll
            for (int mt = 0; mt < 2; mt++)
#pragma unroll
                for (int nt = 0; nt < 4; nt++) {
                    int h = nt >> 1, p = (nt & 1) * 2;
                    mma_bf16(acc[mt][nt], ah[mt], bh[h][p],  bh[h][p + 1]);   // hi*hi
                    mma_bf16(acc[mt][nt], ah[mt], blo[h][p], blo[h][p + 1]);  // hi*lo
                    mma_bf16(acc[mt][nt], al[mt], bh[h][p],  bh[h][p + 1]);   // lo*hi
                }
        }

        // ---- epilogue for this group ----
        float* outp; int colbase; int with_bias;
        if (g < 2)      { outp = Y;  colbase = g * 64;          with_bias = 1; }
        else if (g < 4) { outp = Z1; colbase = (g - 2) * 64;    with_bias = 0; }
        else            { outp = Z2; colbase = (g - 4) * 64;    with_bias = 0; }

#pragma unroll
        for (int mt = 0; mt < 2; mt++) {
            int R = row0 + mgrp * 32 + mt * 16 + (lane >> 2);
#pragma unroll
            for (int nt = 0; nt < 4; nt++) {
                int c = colbase + ngrp * 32 + nt * 8 + 2 * (lane & 3);
                float b0 = 0.0f, b1 = 0.0f;
                if (with_bias) { b0 = bias[g * 64 + ngrp * 32 + nt * 8 + 2 * (lane & 3)];
                                 b1 = bias[g * 64 + ngrp * 32 + nt * 8 + 2 * (lane & 3) + 1]; }
                if (R < N) {
                    float2 v = make_float2(acc[mt][nt][0] + b0, acc[mt][nt][1] + b1);
                    *(float2*)(outp + (size_t)R * DIM + c) = v;
                }
                if (R + 8 < N) {
                    float2 v = make_float2(acc[mt][nt][2] + b0, acc[mt][nt][3] + b1);
                    *(float2*)(outp + (size_t)(R + 8) * DIM + c) = v;
                }
            }
        }
        __syncthreads();   // protect B smem before next group's load
    }
}

// ---------------------------------------------------------------------------
// Readout: sorted graph_ids -> block per graph; relu on load; mean.
// ---------------------------------------------------------------------------
__device__ __forceinline__ int lower_bound_i(const int* a, int n, int v) {
    int lo = 0, hi = n;
    while (lo < hi) { int m = (lo + hi) >> 1; if (a[m] < v) lo = m + 1; else hi = m; }
    return lo;
}
__global__ void readout_kernel(const float* __restrict__ h, const int* __restrict__ gid,
                               float* __restrict__ out, int N) {
    int g = blockIdx.x;
    __shared__ int bounds[2];
    if (threadIdx.x == 0) {
        bounds[0] = lower_bound_i(gid, N, g);
        bounds[1] = lower_bound_i(gid, N, g + 1);
    }
    __syncthreads();
    int lo = bounds[0], hi = bounds[1];
    float s = 0.0f;
    for (int r = lo; r < hi; r++)
        s += fmaxf(h[(size_t)r * DIM + threadIdx.x], 0.0f);
    float cnt = (float)(hi - lo);
    out[(size_t)g * DIM + threadIdx.x] = s / fmaxf(cnt, 1.0f);
}

// ---------------------------------------------------------------------------
extern "C" void kernel_launch(void* const* d_in, const int* in_sizes, int n_in,
                              void* d_out, int out_size) {
    const float* feat = (const float*)d_in[0];   // [N,128]
    const float* W    = (const float*)d_in[1];   // [2,3,128,128]
    const float* b    = (const float*)d_in[2];   // [2,3,128]
    const int*   esrc = (const int*)d_in[3];     // [E]
    const int*   edst = (const int*)d_in[4];     // [E]
    const int*   gids = (const int*)d_in[5];     // [N] sorted

    const int N = in_sizes[0] / DIM;
    const int E = in_sizes[3];
    const int G = out_size / DIM;

    float *y, *z1, *z2, *odeg, *ideg;
    uint4* wp;
    cudaGetSymbolAddress((void**)&y,    g_y);
    cudaGetSymbolAddress((void**)&z1,   g_z1);
    cudaGetSymbolAddress((void**)&z2,   g_z2);
    cudaGetSymbolAddress((void**)&odeg, g_outdeg);
    cudaGetSymbolAddress((void**)&ideg, g_indeg);
    cudaGetSymbolAddress((void**)&wp,   g_wpack);

    cudaFuncSetAttribute(gemm3_kernel,
                         cudaFuncAttributeMaxDynamicSharedMemorySize, GEMM_SMEM);

    prepack_kernel<<<(2 * 384 * 128 + 255) / 256, 256>>>(W);

    cudaMemsetAsync(odeg, 0, (size_t)N * sizeof(float));
    cudaMemsetAsync(ideg, 0, (size_t)N * sizeof(float));
    degree_kernel<<<(E + 255) / 256, 256>>>(esrc, edst, odeg, ideg, E);
    norm_kernel<<<(N + 255) / 256, 256>>>(odeg, ideg, N);

    const int tiles = (N + TILE_M - 1) / TILE_M;
    const int spmm_blocks = (int)(((long long)E * 32 + 255) / 256);
    const float* hin = feat;
    for (int l = 0; l < 2; l++) {
        gemm3_kernel<<<tiles, 256, GEMM_SMEM>>>(
            hin, wp + (size_t)l * 6 * 2048, b + (size_t)l * 3 * 128,
            y, z1, z2, N, l > 0 ? 1 : 0);
        spmm_kernel<<<spmm_blocks, 256>>>(z1, z2, esrc, edst, odeg, ideg, y, E);
        hin = y;
    }

    readout_kernel<<<G, DIM>>>(y, gids, (float*)d_out, N);
}

// round 6
// speedup vs baseline: 2.8382x; 1.4105x over previous
#include <cuda_runtime.h>
#include <cuda_fp16.h>
#include <cstdint>

// ---------------------------------------------------------------------------
// HeteroGraph: 2-layer GraphConv (loop + fwd + rev relations) + mean readout.
// Restructured per layer (spmm commutes with dense matmul):
//   GEMM:  Y = act(h)@W0 + (b0+b1+b2) ;  Z1 = act(h)@W1 ; Z2 = act(h)@W2
//   SPMM:  Y[dst] += c*Z1[src] ;  Y[src] += c*Z2[dst]   (c = n_out[s]*n_in[d])
// act = relu for layer>0. Readout applies final relu.
// GEMM: mma.sync fp16, 2-term split (A=hi+lo fp16, B=fp16) fp32 accumulate.
// SPMM: vector red.global.add.v4.f32 scatter.
// ---------------------------------------------------------------------------

#define DIM 128
#define NMAX 500128
#define TILE_M 128

// smem: A_hi 32K | A_lo 32K | B 2x16K | bias 512
#define SM_AHI 0
#define SM_ALO 32768
#define SM_B   65536
#define SM_BIAS 98304
#define GEMM_SMEM (98304 + 512)

// Static scratch
__device__ float g_y[(size_t)NMAX * DIM];
__device__ float g_z1[(size_t)NMAX * DIM];
__device__ float g_z2[(size_t)NMAX * DIM];
__device__ float g_outdeg[NMAX];
__device__ float g_indeg[NMAX];
// Prepacked W^T fp16 images: [layer][group(6)][16KB]; group = 64 output cols
__device__ uint4 g_wpack[2][6][1024];

// ---------------------------------------------------------------------------
__device__ __forceinline__ uint32_t smem_u32(const void* p) {
    uint32_t a;
    asm("{ .reg .u64 t; cvta.to.shared.u64 t, %1; cvt.u32.u64 %0, t; }" : "=r"(a) : "l"(p));
    return a;
}
__device__ __forceinline__ void ldsm4(uint32_t* r, uint32_t addr) {
    asm volatile("ldmatrix.sync.aligned.m8n8.x4.shared.b16 {%0,%1,%2,%3}, [%4];"
                 : "=r"(r[0]), "=r"(r[1]), "=r"(r[2]), "=r"(r[3]) : "r"(addr));
}
__device__ __forceinline__ void mma_fp16(float* d, const uint32_t* a, uint32_t b0, uint32_t b1) {
    asm volatile("mma.sync.aligned.m16n8k16.row.col.f32.f16.f16.f32 "
                 "{%0,%1,%2,%3}, {%4,%5,%6,%7}, {%8,%9}, {%0,%1,%2,%3};"
                 : "+f"(d[0]), "+f"(d[1]), "+f"(d[2]), "+f"(d[3])
                 : "r"(a[0]), "r"(a[1]), "r"(a[2]), "r"(a[3]), "r"(b0), "r"(b1));
}
__device__ __forceinline__ unsigned short h16_bits(float v) {
    __half h = __float2half_rn(v);
    return *(unsigned short*)&h;
}
__device__ __forceinline__ float h16_val(unsigned short b) {
    __half h = *(__half*)&b;
    return __half2float(h);
}

// ---------------------------------------------------------------------------
// Prepack W: image rows = output col n (within 64-col group), 256B of K=128 fp16,
// 16B chunks XOR-swizzled by (n&7).
// ---------------------------------------------------------------------------
__global__ void prepack_kernel(const float* __restrict__ W) {
    int idx = blockIdx.x * blockDim.x + threadIdx.x;   // 2*384*128
    if (idx >= 2 * 384 * 128) return;
    int k = idx & 127;
    int J = (idx >> 7) % 384;
    int l = idx / (384 * 128);
    int r = J >> 7, j = J & 127;
    int g = J >> 6, n = J & 63;
    float v = W[(((size_t)l * 3 + r) * 128 + k) * 128 + j];
    uint32_t off = n * 256 + (((k >> 3) ^ (n & 7)) << 4) + (k & 7) * 2;
    *(unsigned short*)((unsigned char*)&g_wpack[l][g][0] + off) = h16_bits(v);
}

// ---------------------------------------------------------------------------
__global__ void degree_kernel(const int* __restrict__ src, const int* __restrict__ dst,
                              float* odeg, float* ideg, int E) {
    int e = blockIdx.x * blockDim.x + threadIdx.x;
    if (e < E) {
        atomicAdd(&odeg[src[e]], 1.0f);
        atomicAdd(&ideg[dst[e]], 1.0f);
    }
}
__global__ void norm_kernel(float* odeg, float* ideg, int N) {
    int i = blockIdx.x * blockDim.x + threadIdx.x;
    if (i < N) {
        float a = odeg[i]; odeg[i] = (a > 0.0f) ? rsqrtf(a) : 0.0f;
        float b = ideg[i]; ideg[i] = (b > 0.0f) ? rsqrtf(b) : 0.0f;
    }
}

// One warp per edge; both directions; vector red straight into Y.
__global__ void spmm_kernel(const float* __restrict__ z1, const float* __restrict__ z2,
                            const int* __restrict__ src, const int* __restrict__ dst,
                            const float* __restrict__ n_out, const float* __restrict__ n_in,
                            float* __restrict__ y, int E) {
    int e = (blockIdx.x * blockDim.x + threadIdx.x) >> 5;
    if (e >= E) return;
    int lane = threadIdx.x & 31;
    int s = src[e];
    int d = dst[e];
    float c = n_out[s] * n_in[d];
    const float4 zs = *(const float4*)(z1 + (size_t)s * DIM + lane * 4);
    const float4 zd = *(const float4*)(z2 + (size_t)d * DIM + lane * 4);
    float* yd = y + (size_t)d * DIM + lane * 4;
    float* ys = y + (size_t)s * DIM + lane * 4;
    asm volatile("red.global.add.v4.f32 [%0], {%1,%2,%3,%4};"
                 :: "l"(yd), "f"(c * zs.x), "f"(c * zs.y), "f"(c * zs.z), "f"(c * zs.w)
                 : "memory");
    asm volatile("red.global.add.v4.f32 [%0], {%1,%2,%3,%4};"
                 :: "l"(ys), "f"(c * zd.x), "f"(c * zd.y), "f"(c * zd.z), "f"(c * zd.w)
                 : "memory");
}

// ---------------------------------------------------------------------------
// Tensor GEMM: per 128-row tile computes [128,384] = act(X)@[128,384]:
// cols 0-127 -> Y (+bias), 128-255 -> Z1, 256-383 -> Z2.
// 8 warps = 4 mgrp x 2 ngrp, warp tile 32x32, 6 groups of 64 cols.
// fp16 2-term: D = Ahi*B + Alo*B. B double-buffered (register prefetch).
// Y may alias X: each CTA reads only its own 128 rows (converted to smem at
// kernel start) and writes them only in epilogues.
// ---------------------------------------------------------------------------
__global__ __launch_bounds__(256, 2) void gemm3_kernel(
    const float* X, const uint4* __restrict__ wpack,   // [6][1024]
    const float* __restrict__ bl,                      // [3,128]
    float* Y, float* __restrict__ Z1, float* __restrict__ Z2,
    int N, int relu_in)
{
    extern __shared__ char smem[];
    const uint32_t sb = smem_u32(smem);
    const int tid = threadIdx.x;
    const int wid = tid >> 5;
    const int lane = tid & 31;
    const int row0 = blockIdx.x * TILE_M;

    // ---- bias sums ----
    if (tid < 128) {
        *(float*)(smem + SM_BIAS + tid * 4) = bl[tid] + bl[128 + tid] + bl[256 + tid];
    }

    // ---- B group 0 -> registers (overlaps A-fill latency) ----
    uint4 pre[4];
#pragma unroll
    for (int t = 0; t < 4; t++) pre[t] = wpack[tid + t * 256];

    // ---- A fill: 128 rows x 128 k fp32 -> hi/lo fp16, swizzled ----
    {
        const int r = tid >> 1;
        const int khalf = (tid & 1) * 64;
        int grow = row0 + r; if (grow > N - 1) grow = N - 1;
        const float* srcp = X + (size_t)grow * DIM + khalf;
#pragma unroll
        for (int c8 = 0; c8 < 8; c8++) {
            float4 va = *(const float4*)(srcp + c8 * 8);
            float4 vb = *(const float4*)(srcp + c8 * 8 + 4);
            float v[8] = {va.x, va.y, va.z, va.w, vb.x, vb.y, vb.z, vb.w};
            if (relu_in) {
#pragma unroll
                for (int i = 0; i < 8; i++) v[i] = fmaxf(v[i], 0.0f);
            }
            unsigned short hb[8], lb[8];
#pragma unroll
            for (int i = 0; i < 8; i++) {
                hb[i] = h16_bits(v[i]);
                lb[i] = h16_bits(v[i] - h16_val(hb[i]));
            }
            uint4 hq, lq;
            hq.x = (uint32_t)hb[0] | ((uint32_t)hb[1] << 16);
            hq.y = (uint32_t)hb[2] | ((uint32_t)hb[3] << 16);
            hq.z = (uint32_t)hb[4] | ((uint32_t)hb[5] << 16);
            hq.w = (uint32_t)hb[6] | ((uint32_t)hb[7] << 16);
            lq.x = (uint32_t)lb[0] | ((uint32_t)lb[1] << 16);
            lq.y = (uint32_t)lb[2] | ((uint32_t)lb[3] << 16);
            lq.z = (uint32_t)lb[4] | ((uint32_t)lb[5] << 16);
            lq.w = (uint32_t)lb[6] | ((uint32_t)lb[7] << 16);
            int cc = (khalf >> 3) + c8;
            int off = r * 256 + ((cc ^ (r & 7)) << 4);
            *(uint4*)(smem + SM_AHI + off) = hq;
            *(uint4*)(smem + SM_ALO + off) = lq;
        }
    }
    // Stage 0 <- B group 0
    {
        uint4* bdst = (uint4*)(smem + SM_B);
#pragma unroll
        for (int t = 0; t < 4; t++) bdst[tid + t * 256] = pre[t];
    }
    __syncthreads();

    const int mgrp = wid & 3;       // row group (32 rows)
    const int ngrp = wid >> 2;      // col group within 64 (32 cols)

    const int arow[2] = { mgrp * 32 + (lane & 15), mgrp * 32 + 16 + (lane & 15) };
    const int ahi16 = lane >> 4;
    const int brow_base = ngrp * 32 + (lane & 7) + ((lane >> 4) & 1) * 8;
    const int bk = (lane >> 3) & 1;

    const float* bias = (const float*)(smem + SM_BIAS);

#pragma unroll 1
    for (int g = 0; g < 6; g++) {
        // prefetch next B group into registers
        if (g < 5) {
            const uint4* ws = wpack + (size_t)(g + 1) * 1024;
#pragma unroll
            for (int t = 0; t < 4; t++) pre[t] = ws[tid + t * 256];
        }

        const uint32_t bbase = sb + SM_B + (uint32_t)(g & 1) * 16384;

        float acc[2][4][4];
#pragma unroll
        for (int mt = 0; mt < 2; mt++)
#pragma unroll
            for (int nt = 0; nt < 4; nt++)
#pragma unroll
                for (int q = 0; q < 4; q++) acc[mt][nt][q] = 0.0f;

#pragma unroll
        for (int ks = 0; ks < 8; ks++) {
            uint32_t ah[2][4], al[2][4], bh[2][4];
#pragma unroll
            for (int mt = 0; mt < 2; mt++) {
                uint32_t co = ((uint32_t)((ks * 2 + ahi16) ^ (arow[mt] & 7))) << 4;
                ldsm4(ah[mt], sb + SM_AHI + arow[mt] * 256 + co);
                ldsm4(al[mt], sb + SM_ALO + arow[mt] * 256 + co);
            }
#pragma unroll
            for (int h = 0; h < 2; h++) {
                int br = brow_base + h * 16;
                uint32_t co = ((uint32_t)((ks * 2 + bk) ^ (br & 7))) << 4;
                ldsm4(bh[h], bbase + br * 256 + co);
            }
#pragma unroll
            for (int mt = 0; mt < 2; mt++)
#pragma unroll
                for (int nt = 0; nt < 4; nt++) {
                    int h = nt >> 1, p = (nt & 1) * 2;
                    mma_fp16(acc[mt][nt], ah[mt], bh[h][p], bh[h][p + 1]);  // hi*B
                    mma_fp16(acc[mt][nt], al[mt], bh[h][p], bh[h][p + 1]);  // lo*B
                }
        }

        // ---- epilogue for this group ----
        float* outp; int colbase; int with_bias;
        if (g < 2)      { outp = Y;  colbase = g * 64;       with_bias = 1; }
        else if (g < 4) { outp = Z1; colbase = (g - 2) * 64; with_bias = 0; }
        else            { outp = Z2; colbase = (g - 4) * 64; with_bias = 0; }

#pragma unroll
        for (int mt = 0; mt < 2; mt++) {
            int R = row0 + mgrp * 32 + mt * 16 + (lane >> 2);
#pragma unroll
            for (int nt = 0; nt < 4; nt++) {
                int c = colbase + ngrp * 32 + nt * 8 + 2 * (lane & 3);   // 0..126
                float b0 = 0.0f, b1 = 0.0f;
                if (with_bias) {
                    b0 = bias[c];
                    b1 = bias[c + 1];
                }
                if (R < N) {
                    float2 v = make_float2(acc[mt][nt][0] + b0, acc[mt][nt][1] + b1);
                    *(float2*)(outp + (size_t)R * DIM + c) = v;
                }
                if (R + 8 < N) {
                    float2 v = make_float2(acc[mt][nt][2] + b0, acc[mt][nt][3] + b1);
                    *(float2*)(outp + (size_t)(R + 8) * DIM + c) = v;
                }
            }
        }

        // ---- publish prefetched B to the other stage ----
        if (g < 5) {
            uint4* bdst = (uint4*)(smem + SM_B + ((g + 1) & 1) * 16384);
#pragma unroll
            for (int t = 0; t < 4; t++) bdst[tid + t * 256] = pre[t];
        }
        __syncthreads();
    }
}

// ---------------------------------------------------------------------------
// Readout: sorted graph_ids -> block per graph; relu on load; mean.
// ---------------------------------------------------------------------------
__device__ __forceinline__ int lower_bound_i(const int* a, int n, int v) {
    int lo = 0, hi = n;
    while (lo < hi) { int m = (lo + hi) >> 1; if (a[m] < v) lo = m + 1; else hi = m; }
    return lo;
}
__global__ void readout_kernel(const float* __restrict__ h, const int* __restrict__ gid,
                               float* __restrict__ out, int N) {
    int g = blockIdx.x;
    __shared__ int bounds[2];
    if (threadIdx.x == 0) {
        bounds[0] = lower_bound_i(gid, N, g);
        bounds[1] = lower_bound_i(gid, N, g + 1);
    }
    __syncthreads();
    int lo = bounds[0], hi = bounds[1];
    float s = 0.0f;
    for (int r = lo; r < hi; r++)
        s += fmaxf(h[(size_t)r * DIM + threadIdx.x], 0.0f);
    float cnt = (float)(hi - lo);
    out[(size_t)g * DIM + threadIdx.x] = s / fmaxf(cnt, 1.0f);
}

// ---------------------------------------------------------------------------
extern "C" void kernel_launch(void* const* d_in, const int* in_sizes, int n_in,
                              void* d_out, int out_size) {
    const float* feat = (const float*)d_in[0];   // [N,128]
    const float* W    = (const float*)d_in[1];   // [2,3,128,128]
    const float* b    = (const float*)d_in[2];   // [2,3,128]
    const int*   esrc = (const int*)d_in[3];     // [E]
    const int*   edst = (const int*)d_in[4];     // [E]
    const int*   gids = (const int*)d_in[5];     // [N] sorted

    const int N = in_sizes[0] / DIM;
    const int E = in_sizes[3];
    const int G = out_size / DIM;

    float *y, *z1, *z2, *odeg, *ideg;
    uint4* wp;
    cudaGetSymbolAddress((void**)&y,    g_y);
    cudaGetSymbolAddress((void**)&z1,   g_z1);
    cudaGetSymbolAddress((void**)&z2,   g_z2);
    cudaGetSymbolAddress((void**)&odeg, g_outdeg);
    cudaGetSymbolAddress((void**)&ideg, g_indeg);
    cudaGetSymbolAddress((void**)&wp,   g_wpack);

    cudaFuncSetAttribute(gemm3_kernel,
                         cudaFuncAttributeMaxDynamicSharedMemorySize, GEMM_SMEM);

    prepack_kernel<<<(2 * 384 * 128 + 255) / 256, 256>>>(W);

    cudaMemsetAsync(odeg, 0, (size_t)N * sizeof(float));
    cudaMemsetAsync(ideg, 0, (size_t)N * sizeof(float));
    degree_kernel<<<(E + 255) / 256, 256>>>(esrc, edst, odeg, ideg, E);
    norm_kernel<<<(N + 255) / 256, 256>>>(odeg, ideg, N);

    const int tiles = (N + TILE_M - 1) / TILE_M;
    const int spmm_blocks = (int)(((long long)E * 32 + 255) / 256);
    const float* hin = feat;
    for (int l = 0; l < 2; l++) {
        gemm3_kernel<<<tiles, 256, GEMM_SMEM>>>(
            hin, wp + (size_t)l * 6 * 1024, b + (size_t)l * 3 * 128,
            y, z1, z2, N, l > 0 ? 1 : 0);
        spmm_kernel<<<spmm_blocks, 256>>>(z1, z2, esrc, edst, odeg, ideg, y, E);
        hin = y;
    }

    readout_kernel<<<G, DIM>>>(y, gids, (float*)d_out, N);
}